// round 1
// baseline (speedup 1.0000x reference)
#include <cuda_runtime.h>
#include <math_constants.h>

#define NC   91
#define CM1  90
#define BIMG 8
#define DET  100
#define NBINS 4096
#define CAP  4096
#define MAXP 4096
#define MAXN (BIMG*MAXP)

// ---------- scratch (static device globals; no allocation) ----------
__device__ float    g_maxv[MAXN];
__device__ float    g_sumexp[MAXN];
__device__ float    g_keyoff[MAXN];
__device__ unsigned g_cksort[MAXN];          // sortable(candkey) per proposal
__device__ unsigned g_hist[BIMG][NBINS];
__device__ unsigned g_tu[BIMG];
__device__ unsigned g_cnt[BIMG];
__device__ unsigned long long g_cand[BIMG][CAP];
__device__ int      g_selp[BIMG][DET];

__device__ __forceinline__ unsigned f2sort(float x) {
    unsigned u = __float_as_uint(x);
    return (u & 0x80000000u) ? ~u : (u | 0x80000000u);
}

// ---------- K0: zero counters/histograms ----------
__global__ void k_zero() {
    int t = blockIdx.x * blockDim.x + threadIdx.x;
    if (t < BIMG * NBINS) ((unsigned*)g_hist)[t] = 0u;
    if (t < BIMG) g_cnt[t] = 0u;
}

// ---------- K1: per-proposal softmax stats + candkey histogram ----------
__global__ void k_stats(const float* __restrict__ lg, int P) {
    int g    = blockIdx.x * (blockDim.x >> 5) + (threadIdx.x >> 5);
    int lane = threadIdx.x & 31;
    int N    = BIMG * P;
    if (g >= N) return;
    const float* row = lg + (long)g * NC;
    const float NEG = __int_as_float(0xff800000);  // -inf
    float v0 = row[lane];                               // 0..31
    float v1 = row[lane + 32];                          // 32..63
    float v2 = (lane + 64 < NC) ? row[lane + 64] : NEG; // 64..90

    float m = fmaxf(fmaxf(v0, v1), v2);
    #pragma unroll
    for (int o = 16; o; o >>= 1) m = fmaxf(m, __shfl_xor_sync(~0u, m, o));

    float s = __expf(v0 - m) + __expf(v1 - m) + __expf(v2 - m);
    #pragma unroll
    for (int o = 16; o; o >>= 1) s += __shfl_xor_sync(~0u, s, o);

    float cm = fmaxf((lane >= 1) ? v0 : NEG, fmaxf(v1, v2));  // classes 1..90
    #pragma unroll
    for (int o = 16; o; o >>= 1) cm = fmaxf(cm, __shfl_xor_sync(~0u, cm, o));

    if (lane == 0) {
        float ko = m + logf(s);
        g_maxv[g]   = m;
        g_sumexp[g] = s;
        g_keyoff[g] = ko;
        unsigned u = f2sort(cm - ko);
        g_cksort[g] = u;
        int img = g / P;
        atomicAdd(&g_hist[img][u >> 20], 1u);
    }
}

// ---------- K2: per-image rank-100 histogram threshold (1 warp/image) ----------
__global__ void k_thresh() {
    int img  = blockIdx.x;
    int lane = threadIdx.x;
    unsigned running = 0;
    for (int base = NBINS - 32; base >= 0; base -= 32) {
        unsigned v = g_hist[img][base + lane];
        unsigned sfx = v;                      // inclusive suffix sum (toward lane 31)
        #pragma unroll
        for (int o = 1; o < 32; o <<= 1) {
            unsigned t = __shfl_down_sync(~0u, sfx, o);
            if (lane + o < 32) sfx += t;
        }
        unsigned total = __shfl_sync(~0u, sfx, 0);
        if (running + total >= DET) {
            unsigned bal = __ballot_sync(~0u, running + sfx >= DET);
            int l = 31 - __clz(bal);           // highest bin whose incl-suffix reaches DET
            if (lane == 0) g_tu[img] = ((unsigned)(base + l)) << 20;
            return;
        }
        running += total;
    }
    if (lane == 0) g_tu[img] = 0u;
}

// ---------- K3: candidate filter with whole-row early exit ----------
__global__ void k_filter(const float* __restrict__ lg, int P) {
    int g    = blockIdx.x * (blockDim.x >> 5) + (threadIdx.x >> 5);
    int lane = threadIdx.x & 31;
    int N    = BIMG * P;
    if (g >= N) return;
    int img = g / P;
    unsigned TU = g_tu[img];
    if (g_cksort[g] < TU) return;             // ~97% of proposals skip here
    int pl = g - img * P;
    float ko = g_keyoff[g], mv = g_maxv[g], se = g_sumexp[g];
    const float* row = lg + (long)g * NC;
    #pragma unroll
    for (int k = 0; k < 3; k++) {
        int c = lane + 32 * k;
        if (c >= 1 && c < NC) {
            float v = row[c];
            if (f2sort(v - ko) >= TU) {
                float score = __expf(v - mv) / se;
                unsigned su  = f2sort(score);
                unsigned idx = (unsigned)(pl * CM1 + (c - 1));
                unsigned pos = atomicAdd(&g_cnt[img], 1u);
                if (pos < CAP)
                    g_cand[img][pos] = ((unsigned long long)(~su) << 32) | idx;
            }
        }
    }
}

// ---------- K4: per-image sort + box decode ----------
__global__ void k_final(const float* __restrict__ reg,
                        const float* __restrict__ props,
                        float* __restrict__ out_boxes, int P) {
    __shared__ unsigned long long s[CAP];
    int img = blockIdx.x, tid = threadIdx.x, nt = blockDim.x;
    int n = (int)min(g_cnt[img], (unsigned)CAP);
    int m = 128; while (m < n) m <<= 1;
    for (int i = tid; i < m; i += nt)
        s[i] = (i < n) ? g_cand[img][i] : ~0ULL;
    __syncthreads();
    for (int k = 2; k <= m; k <<= 1)
        for (int j = k >> 1; j > 0; j >>= 1) {
            for (int i = tid; i < m; i += nt) {
                int ixj = i ^ j;
                if (ixj > i) {
                    unsigned long long a = s[i], b = s[ixj];
                    bool up = ((i & k) == 0);
                    if ((a > b) == up) { s[i] = b; s[ixj] = a; }
                }
            }
            __syncthreads();
        }
    if (tid < DET) {
        unsigned idx = (unsigned)(s[tid] & 0xffffffffu);
        int p = idx / CM1;
        int c = idx % CM1 + 1;
        long gp = (long)img * P + p;
        const float* pr = props + gp * 4;
        float x1 = pr[0], y1 = pr[1], x2 = pr[2], y2 = pr[3];
        float w = x2 - x1, h = y2 - y1;
        float cx = x1 + 0.5f * w, cy = y1 + 0.5f * h;
        const float* r = reg + gp * (4 * NC) + 4 * c;
        const float CLIP = 4.135166556742356f;  // log(1000/16)
        float dx = r[0] / 10.0f, dy = r[1] / 10.0f;
        float dw = fminf(r[2] / 5.0f, CLIP);
        float dh = fminf(r[3] / 5.0f, CLIP);
        float pcx = dx * w + cx, pcy = dy * h + cy;
        float pw = expf(dw) * w, ph = expf(dh) * h;
        float bx1 = pcx - 0.5f * pw, by1 = pcy - 0.5f * ph;
        float bx2 = pcx + 0.5f * pw, by2 = pcy + 0.5f * ph;
        bx1 = fminf(fmaxf(bx1, 0.f), 800.f);
        bx2 = fminf(fmaxf(bx2, 0.f), 800.f);
        by1 = fminf(fmaxf(by1, 0.f), 800.f);
        by2 = fminf(fmaxf(by2, 0.f), 800.f);
        float* o = out_boxes + ((long)img * DET + tid) * 4;
        o[0] = bx1 / 800.f; o[1] = by1 / 800.f;
        o[2] = bx2 / 800.f; o[3] = by2 / 800.f;
        g_selp[img][tid] = p;
    }
}

// ---------- K5: feature gather ----------
__global__ void k_gather(const float* __restrict__ ft,
                         float* __restrict__ outf, int P, int FD4) {
    int b = blockIdx.x / DET, r = blockIdx.x % DET;
    int p = g_selp[b][r];
    const float4* src = (const float4*)(ft + ((long)b * P + p) * (long)(FD4 * 4));
    float4* dst = (float4*)(outf + ((long)b * DET + r) * (long)(FD4 * 4));
    for (int i = threadIdx.x; i < FD4; i += blockDim.x)
        dst[i] = src[i];
}

extern "C" void kernel_launch(void* const* d_in, const int* in_sizes, int n_in,
                              void* d_out, int out_size) {
    const float* lg    = (const float*)d_in[0];
    const float* reg   = (const float*)d_in[1];
    const float* props = (const float*)d_in[2];
    const float* ft    = (const float*)d_in[3];
    int N  = in_sizes[0] / NC;     // 32768
    int P  = N / BIMG;             // 4096
    int FD = in_sizes[3] / N;      // 1024
    float* out_boxes = (float*)d_out;
    float* out_feats = out_boxes + (long)BIMG * DET * 4;

    k_zero<<<(BIMG * NBINS + 255) / 256, 256>>>();
    int blocks = (N + 7) / 8;                  // 8 warps (256 thr) / block
    k_stats<<<blocks, 256>>>(lg, P);
    k_thresh<<<BIMG, 32>>>();
    k_filter<<<blocks, 256>>>(lg, P);
    k_final<<<BIMG, 1024>>>(reg, props, out_boxes, P);
    k_gather<<<BIMG * DET, 256>>>(ft, out_feats, P, FD / 4);
}

// round 2
// speedup vs baseline: 1.3308x; 1.3308x over previous
#include <cuda_runtime.h>

#define NC    91
#define CM1   90
#define BIMG  8
#define DET   100
#define NBINS 4096
#define CAP   4096
#define MAXP  4096
#define MAXN  (BIMG*MAXP)
#define NBLK  148
#define NTHR  1024
#define NWRP  (NTHR/32)

// ---------- scratch (static device globals; zero-initialized at load) ----------
__device__ float    g_maxv[MAXN];
__device__ float    g_sumexp[MAXN];
__device__ float    g_keyoff[MAXN];
__device__ unsigned g_cksort[MAXN];
__device__ unsigned g_hist[BIMG][NBINS];
__device__ unsigned g_cnt[BIMG];
__device__ unsigned long long g_cand[BIMG][CAP];
__device__ int      g_selp[BIMG][DET];
__device__ unsigned g_bar_cnt;
__device__ unsigned g_bar_gen;

__device__ __forceinline__ unsigned f2sort(float x) {
    unsigned u = __float_as_uint(x);
    return (u & 0x80000000u) ? ~u : (u | 0x80000000u);
}

__device__ __forceinline__ void grid_barrier() {
    __syncthreads();
    if (threadIdx.x == 0) {
        __threadfence();
        unsigned gen = *((volatile unsigned*)&g_bar_gen);
        unsigned arrived = atomicAdd(&g_bar_cnt, 1u);
        if (arrived == (unsigned)(gridDim.x - 1)) {
            g_bar_cnt = 0;
            __threadfence();
            atomicExch(&g_bar_gen, gen + 1u);
        } else {
            while (*((volatile unsigned*)&g_bar_gen) == gen) { __nanosleep(32); }
        }
    }
    __syncthreads();
}

__global__ void __launch_bounds__(NTHR, 1)
fused_rcnn(const float* __restrict__ lg,
           const float* __restrict__ reg,
           const float* __restrict__ props,
           const float* __restrict__ ft,
           float* __restrict__ out_boxes,
           float* __restrict__ out_feats,
           int P, int FD) {
    __shared__ unsigned long long s_sort[CAP];
    __shared__ unsigned s_tu[BIMG];

    const int tid  = threadIdx.x;
    const int bid  = blockIdx.x;
    const int wid  = tid >> 5;
    const int lane = tid & 31;
    const int N    = BIMG * P;
    const int gwarp = bid * NWRP + wid;
    const int nwarp = NBLK * NWRP;
    const float NEG = __int_as_float(0xff800000);  // -inf

    // ================= Phase A: per-proposal softmax stats + candkey histogram =================
    for (int g = gwarp; g < N; g += nwarp) {
        const float* row = lg + (long)g * NC;
        float v0 = row[lane];
        float v1 = row[lane + 32];
        float v2 = (lane + 64 < NC) ? row[lane + 64] : NEG;

        float m = fmaxf(fmaxf(v0, v1), v2);
        #pragma unroll
        for (int o = 16; o; o >>= 1) m = fmaxf(m, __shfl_xor_sync(~0u, m, o));

        float s = __expf(v0 - m) + __expf(v1 - m) + __expf(v2 - m);
        #pragma unroll
        for (int o = 16; o; o >>= 1) s += __shfl_xor_sync(~0u, s, o);

        float cm = fmaxf((lane >= 1) ? v0 : NEG, fmaxf(v1, v2));  // classes 1..90
        #pragma unroll
        for (int o = 16; o; o >>= 1) cm = fmaxf(cm, __shfl_xor_sync(~0u, cm, o));

        if (lane == 0) {
            float ko = m + logf(s);
            g_maxv[g]   = m;
            g_sumexp[g] = s;
            g_keyoff[g] = ko;
            unsigned u  = f2sort(cm - ko);
            g_cksort[g] = u;
            atomicAdd(&g_hist[g / P][u >> 20], 1u);
        }
    }

    grid_barrier();

    // ================= Phase B: per-block redundant rank-100 threshold =================
    // Keys are strictly negative (log p_max < 0), so their sortable codes < 0x80000000
    // -> bins < 2048. Scan bins [0,2048) from the top.
    if (wid < BIMG) {
        const int im = wid;
        unsigned running = 0;
        unsigned tu = 0;
        for (int base = 2048 - 32; base >= 0; base -= 32) {
            unsigned v = g_hist[im][base + lane];
            unsigned sfx = v;  // inclusive suffix sum toward lane 31
            #pragma unroll
            for (int o = 1; o < 32; o <<= 1) {
                unsigned t = __shfl_down_sync(~0u, sfx, o);
                if (lane + o < 32) sfx += t;
            }
            unsigned total = __shfl_sync(~0u, sfx, 0);
            if (running + total >= DET) {
                unsigned bal = __ballot_sync(~0u, running + sfx >= DET);
                int l = 31 - __clz(bal);
                tu = ((unsigned)(base + l)) << 20;
                break;
            }
            running += total;
        }
        if (lane == 0) s_tu[im] = tu;
    }
    __syncthreads();

    // ================= Phase C: candidate filter (1 thread / proposal, row early-exit) =====
    {
        int g = bid * NTHR + tid;
        if (g < N) {
            int img = g / P;
            unsigned TU = s_tu[img];
            if (g_cksort[g] >= TU) {
                int   pl = g - img * P;
                float ko = g_keyoff[g], mv = g_maxv[g], se = g_sumexp[g];
                const float* row = lg + (long)g * NC;
                #pragma unroll 10
                for (int c = 1; c < NC; c++) {
                    float v = __ldg(row + c);
                    if (f2sort(v - ko) >= TU) {
                        float score = __expf(v - mv) / se;
                        unsigned su  = f2sort(score);
                        unsigned idx = (unsigned)(pl * CM1 + (c - 1));
                        unsigned pos = atomicAdd(&g_cnt[img], 1u);
                        if (pos < CAP)
                            g_cand[img][pos] = ((unsigned long long)(~su) << 32) | idx;
                    }
                }
            }
        }
    }

    grid_barrier();

    // ================= Phase D: per-image sort + box decode (blocks 0..7) =================
    if (bid < BIMG) {
        const int img = bid;
        int n = (int)min(g_cnt[img], (unsigned)CAP);
        int m = 128; while (m < n) m <<= 1;
        for (int i = tid; i < m; i += NTHR)
            s_sort[i] = (i < n) ? g_cand[img][i] : ~0ULL;
        __syncthreads();
        for (int k = 2; k <= m; k <<= 1)
            for (int j = k >> 1; j > 0; j >>= 1) {
                for (int i = tid; i < m; i += NTHR) {
                    int ixj = i ^ j;
                    if (ixj > i) {
                        unsigned long long a = s_sort[i], b = s_sort[ixj];
                        bool up = ((i & k) == 0);
                        if ((a > b) == up) { s_sort[i] = b; s_sort[ixj] = a; }
                    }
                }
                __syncthreads();
            }
        if (tid < DET) {
            unsigned idx = (unsigned)(s_sort[tid] & 0xffffffffu);
            int p = idx / CM1;
            int c = idx % CM1 + 1;
            long gp = (long)img * P + p;
            const float* pr = props + gp * 4;
            float x1 = pr[0], y1 = pr[1], x2 = pr[2], y2 = pr[3];
            float w = x2 - x1, h = y2 - y1;
            float cx = x1 + 0.5f * w, cy = y1 + 0.5f * h;
            const float* r = reg + gp * (4 * NC) + 4 * c;
            const float CLIP = 4.135166556742356f;  // log(1000/16)
            float dx = r[0] / 10.0f, dy = r[1] / 10.0f;
            float dw = fminf(r[2] / 5.0f, CLIP);
            float dh = fminf(r[3] / 5.0f, CLIP);
            float pcx = dx * w + cx, pcy = dy * h + cy;
            float pw = expf(dw) * w, ph = expf(dh) * h;
            float bx1 = pcx - 0.5f * pw, by1 = pcy - 0.5f * ph;
            float bx2 = pcx + 0.5f * pw, by2 = pcy + 0.5f * ph;
            bx1 = fminf(fmaxf(bx1, 0.f), 800.f);
            bx2 = fminf(fmaxf(bx2, 0.f), 800.f);
            by1 = fminf(fmaxf(by1, 0.f), 800.f);
            by2 = fminf(fmaxf(by2, 0.f), 800.f);
            float* o = out_boxes + ((long)img * DET + tid) * 4;
            o[0] = bx1 / 800.f; o[1] = by1 / 800.f;
            o[2] = bx2 / 800.f; o[3] = by2 / 800.f;
            g_selp[img][tid] = p;
        }
        __syncthreads();
        if (tid == 0) g_cnt[img] = 0;   // reset for next graph replay
    }

    grid_barrier();

    // ================= Phase E: feature gather (flat float4 copy) + scratch reset =========
    {
        const int FD4 = FD >> 2;                     // 256
        const long total4 = (long)BIMG * DET * FD4;  // 204800
        const int gtid = bid * NTHR + tid;
        const int nthr = NBLK * NTHR;
        for (long i = gtid; i < total4; i += nthr) {
            int  col = (int)(i & (FD4 - 1));
            int  det = (int)(i >> 8);                // FD4 == 256
            int  b   = det / DET;
            int  r   = det - b * DET;
            int  p   = g_selp[b][r];
            const float4* src = (const float4*)(ft + ((long)b * P + p) * FD);
            float4* dst = (float4*)(out_feats + (long)det * FD);
            dst[col] = src[col];
        }
        // reset histogram for the next replay
        for (int i = gtid; i < BIMG * NBINS; i += nthr)
            ((unsigned*)g_hist)[i] = 0u;
    }
}

extern "C" void kernel_launch(void* const* d_in, const int* in_sizes, int n_in,
                              void* d_out, int out_size) {
    const float* lg    = (const float*)d_in[0];
    const float* reg   = (const float*)d_in[1];
    const float* props = (const float*)d_in[2];
    const float* ft    = (const float*)d_in[3];
    int N  = in_sizes[0] / NC;     // 32768
    int P  = N / BIMG;             // 4096
    int FD = in_sizes[3] / N;      // 1024
    float* out_boxes = (float*)d_out;
    float* out_feats = out_boxes + (long)BIMG * DET * 4;

    fused_rcnn<<<NBLK, NTHR>>>(lg, reg, props, ft, out_boxes, out_feats, P, FD);
}